// round 1
// baseline (speedup 1.0000x reference)
#include <cuda_runtime.h>

#define GN   128
#define GN2  (GN * GN)
#define GN3  (GN * GN * GN)
#define BIGV 1.0e5f

// Scratch ping-pong buffers (allocation-free rule: __device__ globals).
__device__ float g_bufA[GN3];
__device__ float g_bufB[GN3];

__global__ void __launch_bounds__(512) eik_step(
    const float* __restrict__ src,
    const float* __restrict__ f,
    float* __restrict__ dst)
{
    const int k = threadIdx.x;                          // contiguous axis, coalesced
    const int j = blockIdx.y * blockDim.y + threadIdx.y;
    const int i = blockIdx.z;
    const int idx = (i * GN + j) * GN + k;

    const float u  = src[idx];
    const float xm = (i > 0)      ? src[idx - GN2] : BIGV;
    const float xp = (i < GN - 1) ? src[idx + GN2] : BIGV;
    const float ym = (j > 0)      ? src[idx - GN]  : BIGV;
    const float yp = (j < GN - 1) ? src[idx + GN]  : BIGV;
    const float zm = (k > 0)      ? src[idx - 1]   : BIGV;
    const float zp = (k < GN - 1) ? src[idx + 1]   : BIGV;

    const float ax = fminf(xm, xp);
    const float ay = fminf(ym, yp);
    const float az = fminf(zm, zp);

    // Exact 3-element sort via min/max network (matches jnp.sort semantics)
    const float a1 = fminf(ax, fminf(ay, az));
    const float a3 = fmaxf(ax, fmaxf(ay, az));
    const float a2 = fmaxf(fminf(ax, ay), fminf(fmaxf(ax, ay), az));

    float out = u;
    // Monotone update: x >= a1 always (fh >= 0.5), so a1 >= u => min(u,x) == u.
    if (a1 < u) {
        const float fh = f[idx];                        // h == 1.0
        const float x1 = a1 + fh;
        float x;
        if (x1 <= a2) {
            x = x1;
        } else {
            const float d  = a1 - a2;
            const float d2 = 2.0f * fh * fh - d * d;
            const float x2 = 0.5f * (a1 + a2 + sqrtf(fmaxf(d2, 0.0f)));
            if (x2 <= a3) {
                x = x2;
            } else {
                const float s  = a1 + a2 + a3;
                const float q  = a1 * a1 + a2 * a2 + a3 * a3;
                const float d3 = s * s - 3.0f * (q - fh * fh);
                x = (s + sqrtf(fmaxf(d3, 0.0f))) / 3.0f;
            }
        }
        out = fminf(u, x);
    }
    dst[idx] = out;
}

extern "C" void kernel_launch(void* const* d_in, const int* in_sizes, int n_in,
                              void* d_out, int out_size)
{
    const float* u0 = (const float*)d_in[0];
    const float* f  = (const float*)d_in[1];
    float* out      = (float*)d_out;

    float* bufA = nullptr;
    float* bufB = nullptr;
    cudaGetSymbolAddress((void**)&bufA, g_bufA);
    cudaGetSymbolAddress((void**)&bufB, g_bufB);

    const dim3 blk(128, 4, 1);
    const dim3 grd(1, GN / 4, GN);

    const float* src = u0;
    for (int it = 0; it < 128; ++it) {
        float* dst = (it == 127) ? out : ((it & 1) ? bufB : bufA);
        eik_step<<<grd, blk>>>(src, f, dst);
        src = dst;
    }
}

// round 2
// speedup vs baseline: 1.4794x; 1.4794x over previous
#include <cuda_runtime.h>

#define GN   128
#define GN2  (GN * GN)
#define GN3  (GN * GN * GN)
#define BIGV 1.0e5f

// Scratch ping-pong buffers (allocation-free rule: __device__ globals).
__device__ float g_bufA[GN3];
__device__ float g_bufB[GN3];

__global__ void __launch_bounds__(256) eik_step(
    const float* __restrict__ src,
    const float* __restrict__ f,
    float* __restrict__ dst)
{
    const int lane = threadIdx.x;                      // 0..31, covers k in float4s
    const int j = blockIdx.y * 8 + threadIdx.y;
    const int i = blockIdx.z;
    const int idx = (i * GN + j) * GN + lane * 4;

    const float4 big4 = make_float4(BIGV, BIGV, BIGV, BIGV);

    const float4 uc  = *(const float4*)(src + idx);
    const float4 xm4 = (i > 0)      ? *(const float4*)(src + idx - GN2) : big4;
    const float4 xp4 = (i < GN - 1) ? *(const float4*)(src + idx + GN2) : big4;
    const float4 ym4 = (j > 0)      ? *(const float4*)(src + idx - GN)  : big4;
    const float4 yp4 = (j < GN - 1) ? *(const float4*)(src + idx + GN)  : big4;

    // z-edge neighbors across lanes (warp is exactly one k-row)
    float left  = __shfl_up_sync(0xffffffffu, uc.w, 1);
    float right = __shfl_down_sync(0xffffffffu, uc.x, 1);
    if (lane == 0)      left  = BIGV;
    if (lane == 31)     right = BIGV;

    const float* ucp = (const float*)&uc;
    const float* xmp = (const float*)&xm4;
    const float* xpp = (const float*)&xp4;
    const float* ymp = (const float*)&ym4;
    const float* ypp = (const float*)&yp4;

    float u[4], a1[4], a2[4], a3[4];
    bool  act[4];
    bool  anyact = false;

    #pragma unroll
    for (int c = 0; c < 4; ++c) {
        u[c] = ucp[c];
        const float zm = (c == 0) ? left  : ucp[c - 1];
        const float zp = (c == 3) ? right : ucp[c + 1];
        const float ax = fminf(xmp[c], xpp[c]);
        const float ay = fminf(ymp[c], ypp[c]);
        const float az = fminf(zm, zp);
        // exact 3-sort via min/max net (matches jnp.sort)
        a1[c] = fminf(ax, fminf(ay, az));
        a3[c] = fmaxf(ax, fmaxf(ay, az));
        a2[c] = fmaxf(fminf(ax, ay), fminf(fmaxf(ax, ay), az));
        // monotone: x >= a1 (fh >= 0.5) so a1 >= u => no change
        act[c] = (a1[c] < u[c]);
        anyact |= act[c];
    }

    float4 res = uc;
    float* rp = (float*)&res;

    if (anyact) {
        const float4 f4 = *(const float4*)(f + idx);
        const float* fp = (const float*)&f4;
        #pragma unroll
        for (int c = 0; c < 4; ++c) {
            if (!act[c]) continue;
            const float fh = fp[c];                     // h == 1.0
            const float x1 = a1[c] + fh;
            float x;
            if (x1 <= a2[c]) {
                x = x1;
            } else {
                const float d  = a1[c] - a2[c];
                const float d2 = 2.0f * fh * fh - d * d;
                const float x2 = 0.5f * (a1[c] + a2[c] + sqrtf(fmaxf(d2, 0.0f)));
                if (x2 <= a3[c]) {
                    x = x2;
                } else {
                    const float s  = a1[c] + a2[c] + a3[c];
                    const float q  = a1[c] * a1[c] + a2[c] * a2[c] + a3[c] * a3[c];
                    const float d3 = s * s - 3.0f * (q - fh * fh);
                    x = (s + sqrtf(fmaxf(d3, 0.0f))) / 3.0f;
                }
            }
            rp[c] = fminf(u[c], x);
        }
    }

    *(float4*)(dst + idx) = res;
}

extern "C" void kernel_launch(void* const* d_in, const int* in_sizes, int n_in,
                              void* d_out, int out_size)
{
    const float* u0 = (const float*)d_in[0];
    const float* f  = (const float*)d_in[1];
    float* out      = (float*)d_out;

    float* bufA = nullptr;
    float* bufB = nullptr;
    cudaGetSymbolAddress((void**)&bufA, g_bufA);
    cudaGetSymbolAddress((void**)&bufB, g_bufB);

    const dim3 blk(32, 8, 1);
    const dim3 grd(1, GN / 8, GN);

    const float* src = u0;
    for (int it = 0; it < 128; ++it) {
        float* dst = (it == 127) ? out : ((it & 1) ? bufB : bufA);
        eik_step<<<grd, blk>>>(src, f, dst);
        src = dst;
    }
}